// round 12
// baseline (speedup 1.0000x reference)
#include <cuda_runtime.h>

#define NG   512
#define S    128
#define FENC 16777216.0          // 2^24 fixed-point encode grain
#define FDEC 8388608.0           // 2^23 decode: /2 gap applies pair-symmetry x2
#define CNT_BIT 54
#define SUM_MASK ((1ULL << CNT_BIT) - 1ULL)

__device__ unsigned long long g_acc = 0ULL;   // bits[0,54): fx sum, bits[54+): count

// 512 CTAs x 256 threads (CTA = one group). Round-11 champion +:
//  * __launch_bounds__(256,4): 64 regs/thread (was 32) — room for software
//    pipelining of the unrolled pair loop. Occupancy unchanged (4 CTAs/SM,
//    512 CTAs all resident in one wave).
//  * Explicit ILP=2: iterations (k, k+16) interleaved with independent
//    accumulators, so two dependency chains (incl. the 16-cyc MUFU sqrt)
//    are always in flight per thread.
// Rest identical to r11: per-warp dtype detection, speculative int32-view
// positions, SMEM float4/float2 row cache with rows 0..63 duplicated,
// (sqrt a - sqrt b)^2 = a+b-2*sqrt(ab) via sqrt.approx (sqrt(0)=0 matches
// the grad-safe pdist), d=64 pair weighted once, single packed-atomic tail.
__global__ void __launch_bounds__(256, 4)
loss_kernel(const float* __restrict__ inputs,
            const float* __restrict__ target,
            const void*  __restrict__ positions,
            float* __restrict__ out) {
    __shared__ float4 A[S + 64];
    __shared__ float2 B[S + 64];
    __shared__ float  wsum[8];

    const int tid = threadIdx.x;
    const int g   = blockIdx.x;
    const int row = tid & (S - 1);
    const int h   = tid >> 7;

    // ---- positions + per-warp dtype detection (threads < 128) ----
    if (tid < S) {
        const unsigned* pw = (const unsigned*)positions;
        const unsigned p32 = pw[g * S + tid];                 // speculative
        const unsigned chk = pw[129 + 2 * (tid & 31)];        // <1KB, safe
        const unsigned any = __ballot_sync(0xffffffffu, chk != 0u);
        int p = (int)p32;
        if (any == 0u)                                        // int64 layout
            p = (int)((const long long*)positions)[g * S + tid];

        const float* xr = inputs + (size_t)p * 9 + 3;         // CA = frame row 1
        const float* tr = target + (size_t)p * 9 + 3;
        const float4 av = make_float4(xr[0], xr[1], xr[2], tr[0]);
        const float2 bv = make_float2(tr[1], tr[2]);
        A[tid] = av;  B[tid] = bv;
        if (tid < 64) { A[tid + S] = av; B[tid + S] = bv; }
    }
    __syncthreads();

    // ---- pair loop: d = 1+32h .. 32+32h, j = row + d; ILP=2 ----
    const float4 av = A[row];
    const float2 bv = B[row];
    const float4* qa = &A[row + 1 + 32 * h];
    const float2* qb = &B[row + 1 + 32 * h];
    const float xi0 = av.x, xi1 = av.y, xi2 = av.z;
    const float ti0 = av.w, ti1 = bv.x, ti2 = bv.y;
    const float wLast = (h == 1 && row >= 64) ? 0.0f : 1.0f;  // d=64 pair once

    float accA0 = 0.f, accB0 = 0.f, accS0 = 0.f;
    float accA1 = 0.f, accB1 = 0.f, accS1 = 0.f;

#pragma unroll
    for (int k = 0; k < 16; ++k) {
        // chain 0: j-offset k
        {
            const float4 va = qa[k];
            const float2 vb = qb[k];
            const float dx0 = va.x - xi0, dx1 = va.y - xi1, dx2 = va.z - xi2;
            const float a = dx0 * dx0 + dx1 * dx1 + dx2 * dx2;
            const float dt0 = va.w - ti0, dt1 = vb.x - ti1, dt2 = vb.y - ti2;
            const float b = dt0 * dt0 + dt1 * dt1 + dt2 * dt2;
            float sq;
            asm("sqrt.approx.f32 %0, %1;" : "=f"(sq) : "f"(a * b));
            accA0 += a; accB0 += b; accS0 += sq;
        }
        // chain 1: j-offset k+16 (k==15 is d=32+32h -> weighted)
        {
            const float4 va = qa[k + 16];
            const float2 vb = qb[k + 16];
            const float dx0 = va.x - xi0, dx1 = va.y - xi1, dx2 = va.z - xi2;
            const float a = dx0 * dx0 + dx1 * dx1 + dx2 * dx2;
            const float dt0 = va.w - ti0, dt1 = vb.x - ti1, dt2 = vb.y - ti2;
            const float b = dt0 * dt0 + dt1 * dt1 + dt2 * dt2;
            float sq;
            asm("sqrt.approx.f32 %0, %1;" : "=f"(sq) : "f"(a * b));
            if (k == 15) {
                accA1 = fmaf(wLast, a,  accA1);
                accB1 = fmaf(wLast, b,  accB1);
                accS1 = fmaf(wLast, sq, accS1);
            } else {
                accA1 += a; accB1 += b; accS1 += sq;
            }
        }
    }
    float acc = ((accA0 + accA1) + (accB0 + accB1))
              - 2.0f * (accS0 + accS1);

    // ---- block reduction (8 warps) ----
#pragma unroll
    for (int off = 16; off > 0; off >>= 1)
        acc += __shfl_xor_sync(0xffffffffu, acc, off);
    const int lane = tid & 31, warp = tid >> 5;
    if (lane == 0) wsum[warp] = acc;
    __syncthreads();

    // ---- single packed-atomic tail (tid 0 only) ----
    if (tid == 0) {
        float s = 0.0f;
#pragma unroll
        for (int w = 0; w < 8; ++w) s += wsum[w];
        s = fmaxf(s, 0.0f);                       // guard the count field
        const unsigned long long fx =
            (unsigned long long)(long long)((double)s * FENC);
        const unsigned long long add = fx + (1ULL << CNT_BIT);
        const unsigned long long old = atomicAdd(&g_acc, add);
        if ((old >> CNT_BIT) == (unsigned long long)(NG - 1)) {
            const unsigned long long tot = (old & SUM_MASK) + fx;
            out[0] = (float)((double)tot / FDEC / ((double)NG * S * S));
            g_acc = 0ULL;                          // reset for next replay
        }
    }
}

extern "C" void kernel_launch(void* const* d_in, const int* in_sizes, int n_in,
                              void* d_out, int out_size) {
    const float* inputs    = (const float*)d_in[0];
    const float* target    = (const float*)d_in[1];
    const void*  positions = d_in[2];
    loss_kernel<<<NG, 256>>>(inputs, target, positions, (float*)d_out);
}

// round 13
// speedup vs baseline: 1.0029x; 1.0029x over previous
#include <cuda_runtime.h>

#define NG   512
#define S    128
#define FENC 16777216.0          // 2^24 fixed-point encode grain
#define FDEC 8388608.0           // 2^23 decode: /2 gap applies pair-symmetry x2
#define CNT_BIT 54
#define SUM_MASK ((1ULL << CNT_BIT) - 1ULL)

__device__ unsigned long long g_acc = 0ULL;   // bits[0,54): fx sum, bits[54+): count

// 512 CTAs x 256 threads (CTA = one group).
//  * Norm-expansion pair math: |xi-xj|^2 = n2i + n2j - 2 xi.xj. SMEM per row
//    per tensor: float4(-2x0,-2x1,-2x2, n2) -> per pair/tensor: 1 FADD seed +
//    3 FFMA (16 instr/pair total vs 19, shorter chains). Product clamped at 0
//    before sqrt (duplicate sample indices can round a to -eps; reference is
//    exactly 0 there -> clamp keeps sqrt NaN-free, error ~1e-7 relative).
//  * Gather uses all 256 threads: t<128 loads the inputs row, t>=128 the
//    target row (halves the serial positions->coords chain).
//  * Per-warp dtype detection (odd dwords 129..191, <1KB safe both layouts:
//    group-1 indices nonzero iff int32, zero int64 high-halves iff int64);
//    speculative int32-view positions load.
//  * Rows 0..63 duplicated so j=row+d needs no wraparound; thread
//    (row=t&127, h=t>>7) covers d in [1+32h, 32+32h]; d=64 pair weighted by
//    row<64. (sqrt a - sqrt b)^2 = a+b-2*sqrt(ab), sqrt.approx.
//  * Tail: ONE relaxed u64 atomicAdd packing {fx partial, arrival count};
//    integer adds associative => deterministic; last CTA writes mean+resets.
__global__ void __launch_bounds__(256, 4)
loss_kernel(const float* __restrict__ inputs,
            const float* __restrict__ target,
            const void*  __restrict__ positions,
            float* __restrict__ out) {
    __shared__ float4 A[S + 64];   // inputs: (-2x, n2)
    __shared__ float4 B[S + 64];   // target: (-2t, n2)
    __shared__ float  wsum[8];

    const int tid = threadIdx.x;
    const int g   = blockIdx.x;
    const int row = tid & (S - 1);
    const int h   = tid >> 7;

    // ---- positions (all threads) + per-warp dtype detection ----
    {
        const unsigned* pw = (const unsigned*)positions;
        const unsigned p32 = pw[g * S + row];                 // speculative
        const unsigned chk = pw[129 + 2 * (tid & 31)];        // <1KB, safe
        const unsigned any = __ballot_sync(0xffffffffu, chk != 0u);
        int p = (int)p32;
        if (any == 0u)                                        // int64 layout
            p = (int)((const long long*)positions)[g * S + row];

        // t<128 -> inputs row, t>=128 -> target row (CA = frame row 1)
        const float* src = (h == 0 ? inputs : target) + (size_t)p * 9 + 3;
        const float x0 = src[0], x1 = src[1], x2 = src[2];
        const float n2 = x0 * x0 + x1 * x1 + x2 * x2;
        const float4 v = make_float4(-2.0f * x0, -2.0f * x1, -2.0f * x2, n2);
        float4* dst = (h == 0) ? A : B;
        dst[row] = v;
        if (row < 64) dst[row + S] = v;
    }
    __syncthreads();

    // ---- own row: recover xi = -0.5 * stored, n2i = .w ----
    const float4 ar = A[row];
    const float4 br = B[row];
    const float xi0 = -0.5f * ar.x, xi1 = -0.5f * ar.y, xi2 = -0.5f * ar.z;
    const float ti0 = -0.5f * br.x, ti1 = -0.5f * br.y, ti2 = -0.5f * br.z;
    const float n2x = ar.w, n2t = br.w;

    const float4* qa = &A[row + 1 + 32 * h];
    const float4* qb = &B[row + 1 + 32 * h];
    const float wLast = (h == 1 && row >= 64) ? 0.0f : 1.0f;  // d=64 pair once

    float accA = 0.f, accB = 0.f, accSq = 0.f;
#pragma unroll
    for (int jj = 0; jj < 32; ++jj) {
        const float4 va = qa[jj];
        const float4 vb = qb[jj];
        // a = n2x + va.w + (-2xj).xi  (1 FADD + 3 FFMA)
        float a = n2x + va.w;
        a = fmaf(va.x, xi0, a);
        a = fmaf(va.y, xi1, a);
        a = fmaf(va.z, xi2, a);
        float b = n2t + vb.w;
        b = fmaf(vb.x, ti0, b);
        b = fmaf(vb.y, ti1, b);
        b = fmaf(vb.z, ti2, b);
        const float pr = fmaxf(a * b, 0.0f);      // NaN guard for dup rows
        float sq;
        asm("sqrt.approx.f32 %0, %1;" : "=f"(sq) : "f"(pr));
        if (jj == 31) {
            accA += a * wLast; accB += b * wLast; accSq += sq * wLast;
        } else {
            accA += a; accB += b; accSq += sq;
        }
    }
    float acc = (accA + accB) - 2.0f * accSq;

    // ---- block reduction (8 warps) ----
#pragma unroll
    for (int off = 16; off > 0; off >>= 1)
        acc += __shfl_xor_sync(0xffffffffu, acc, off);
    const int lane = tid & 31, warp = tid >> 5;
    if (lane == 0) wsum[warp] = acc;
    __syncthreads();

    // ---- single packed-atomic tail (tid 0 only) ----
    if (tid == 0) {
        float s = 0.0f;
#pragma unroll
        for (int w = 0; w < 8; ++w) s += wsum[w];
        s = fmaxf(s, 0.0f);                       // guard the count field
        const unsigned long long fx =
            (unsigned long long)(long long)((double)s * FENC);
        const unsigned long long add = fx + (1ULL << CNT_BIT);
        const unsigned long long old = atomicAdd(&g_acc, add);
        if ((old >> CNT_BIT) == (unsigned long long)(NG - 1)) {
            const unsigned long long tot = (old & SUM_MASK) + fx;
            out[0] = (float)((double)tot / FDEC / ((double)NG * S * S));
            g_acc = 0ULL;                          // reset for next replay
        }
    }
}

extern "C" void kernel_launch(void* const* d_in, const int* in_sizes, int n_in,
                              void* d_out, int out_size) {
    const float* inputs    = (const float*)d_in[0];
    const float* target    = (const float*)d_in[1];
    const void*  positions = d_in[2];
    loss_kernel<<<NG, 256>>>(inputs, target, positions, (float*)d_out);
}

// round 14
// speedup vs baseline: 1.0238x; 1.0208x over previous
#include <cuda_runtime.h>

#define NG   512
#define S    128
#define FENC 16777216.0          // 2^24 fixed-point encode grain
#define FDEC 8388608.0           // 2^23 decode: /2 gap applies pair-symmetry x2
#define CNT_BIT 54
#define SUM_MASK ((1ULL << CNT_BIT) - 1ULL)

__device__ unsigned long long g_acc = 0ULL;   // bits[0,54): fx sum, bits[54+): count

// 512 CTAs x 512 threads (CTA = one group; 4 CTAs/SM = 2048 thr = HW max,
// ~55 resident warps/SM vs ~28 before — the kernel is latency-bound, so
// doubling warps/SMSP fills the LDS/MUFU/LDG latency holes).
//  * thread (row=t&127, q=t>>7 in 0..3) covers d in [1+16q, 16+16q]; each
//    unordered pair once (d=64, i.e. q==3/jj==15, weighted by row<64).
//  * gather: warps 0-3 load inputs rows, warps 4-7 target rows (CA = frame
//    row 1 -> float offset p*9+3); SMEM 24B/row: float4(x0,x1,x2,t0) +
//    float2(t1,t2); rows 0..63 duplicated so j=row+d needs no wraparound.
//  * per-warp dtype detection: odd dwords 129..191 (<1KB, safe under both
//    layouts) are group-1 indices (>=256, nonzero) iff int32, zero int64
//    high-halves iff int64; int32-view positions load is speculative.
//  * (sqrt a - sqrt b)^2 = a + b - 2*sqrt(ab) via sqrt.approx (sqrt(0)=0
//    matches the grad-safe pdist).
//  * tail: ONE relaxed u64 atomicAdd packing {fx partial, arrival count}
//    (integer adds associative => deterministic); last CTA writes the mean
//    and resets the accumulator for graph replay.
__global__ void __launch_bounds__(512, 4)
loss_kernel(const float* __restrict__ inputs,
            const float* __restrict__ target,
            const void*  __restrict__ positions,
            float* __restrict__ out) {
    __shared__ float4 A[S + 64];
    __shared__ float2 B[S + 64];
    __shared__ float  wsum[16];

    const int tid = threadIdx.x;
    const int g   = blockIdx.x;
    const int row = tid & (S - 1);
    const int q   = tid >> 7;          // 0..3

    // ---- gather (warps 0-7): t<128 inputs row, 128<=t<256 target row ----
    if (tid < 2 * S) {
        const unsigned* pw = (const unsigned*)positions;
        const unsigned p32 = pw[g * S + row];                 // speculative
        const unsigned chk = pw[129 + 2 * (tid & 31)];        // <1KB, safe
        const unsigned any = __ballot_sync(0xffffffffu, chk != 0u);
        int p = (int)p32;
        if (any == 0u)                                        // int64 layout
            p = (int)((const long long*)positions)[g * S + row];

        const float* src = (tid < S ? inputs : target) + (size_t)p * 9 + 3;
        const float x0 = src[0], x1 = src[1], x2 = src[2];
        if (tid < S) {
            // inputs -> A.xyz
            A[row].x = x0; A[row].y = x1; A[row].z = x2;
            if (row < 64) { A[row + S].x = x0; A[row + S].y = x1; A[row + S].z = x2; }
        } else {
            // target -> A.w + B
            A[row].w = x0;
            const float2 bv = make_float2(x1, x2);
            B[row] = bv;
            if (row < 64) { A[row + S].w = x0; B[row + S] = bv; }
        }
    }
    __syncthreads();

    // ---- pair loop: d = 1+16q .. 16+16q, j = row + d (no wrap) ----
    const float4 av = A[row];
    const float2 bv = B[row];
    const float4* qa = &A[row + 1 + 16 * q];
    const float2* qb = &B[row + 1 + 16 * q];
    const float xi0 = av.x, xi1 = av.y, xi2 = av.z;
    const float ti0 = av.w, ti1 = bv.x, ti2 = bv.y;
    const float wLast = (q == 3 && row >= 64) ? 0.0f : 1.0f;  // d=64 pair once

    float accA = 0.f, accB = 0.f, accSq = 0.f;
#pragma unroll
    for (int jj = 0; jj < 16; ++jj) {
        const float4 va = qa[jj];
        const float2 vb = qb[jj];
        const float dx0 = va.x - xi0, dx1 = va.y - xi1, dx2 = va.z - xi2;
        const float a = dx0 * dx0 + dx1 * dx1 + dx2 * dx2;
        const float dt0 = va.w - ti0, dt1 = vb.x - ti1, dt2 = vb.y - ti2;
        const float b = dt0 * dt0 + dt1 * dt1 + dt2 * dt2;
        float sq;
        asm("sqrt.approx.f32 %0, %1;" : "=f"(sq) : "f"(a * b));
        if (jj == 15) {
            accA += a * wLast; accB += b * wLast; accSq += sq * wLast;
        } else {
            accA += a; accB += b; accSq += sq;
        }
    }
    float acc = (accA + accB) - 2.0f * accSq;

    // ---- block reduction (16 warps) ----
#pragma unroll
    for (int off = 16; off > 0; off >>= 1)
        acc += __shfl_xor_sync(0xffffffffu, acc, off);
    const int lane = tid & 31, warp = tid >> 5;
    if (lane == 0) wsum[warp] = acc;
    __syncthreads();

    // ---- single packed-atomic tail (tid 0 only) ----
    if (tid == 0) {
        float s = 0.0f;
#pragma unroll
        for (int w = 0; w < 16; ++w) s += wsum[w];
        s = fmaxf(s, 0.0f);                       // guard the count field
        const unsigned long long fx =
            (unsigned long long)(long long)((double)s * FENC);
        const unsigned long long add = fx + (1ULL << CNT_BIT);
        const unsigned long long old = atomicAdd(&g_acc, add);
        if ((old >> CNT_BIT) == (unsigned long long)(NG - 1)) {
            const unsigned long long tot = (old & SUM_MASK) + fx;
            out[0] = (float)((double)tot / FDEC / ((double)NG * S * S));
            g_acc = 0ULL;                          // reset for next replay
        }
    }
}

extern "C" void kernel_launch(void* const* d_in, const int* in_sizes, int n_in,
                              void* d_out, int out_size) {
    const float* inputs    = (const float*)d_in[0];
    const float* target    = (const float*)d_in[1];
    const void*  positions = d_in[2];
    loss_kernel<<<NG, 512>>>(inputs, target, positions, (float*)d_out);
}